// round 14
// baseline (speedup 1.0000x reference)
#include <cuda_runtime.h>
#include <cuda_bf16.h>
#include <cfloat>

// ---------------------------------------------------------------------------
// VectorQuantizer (VQ-VAE) fused pipeline, sm_100.
// R13 -> R14: passA profile showed tensor=10.7%, occ=21.6%, issue=14.9% --
// latency-bound at 1.7 CTAs/SM (grid 256), NOT throughput-bound. Fix: split
// the code dimension 4x across CTAs (grid 1024, 8 chunks each, 3 CTAs/SM
// resident). Winner-collection stays safe: the winner's CTA always collects
// it (local running min >= winner's score); other CTAs only over-collect.
// Everything else byte-identical to the 342us R13 kernel.
// ---------------------------------------------------------------------------

#define NROWS 32768
#define KN    4096
#define DIM   64

// pass A tiling
#define AM    128            // rows per CTA
#define SPLITK 4             // code-range splits per row block
#define KPART (KN / SPLITK)  // 1024 codes per CTA
#define ABLK  ((NROWS / AM) * SPLITK)   // 1024 CTAs
#define ACH   128            // codes per chunk
#define NCHS  (KPART / ACH)  // 8 chunks per CTA
#define LDT   72             // smem tile row stride (halves): conflict-free ldmatrix
#define MARGIN 6e-4f
#define CAND_CAP (1u << 22)  // 4M candidate slots

// output offsets (elements)
#define O_ZQ   0
#define O_IND  2097152
#define O_LOSS 2129920
#define O_NE   2129921
#define O_NCS  2392065
#define O_NW   2396161

// scratch
__device__ float              g_zz[NROWS];
__device__ float              g_e2[KN];
__device__ float              g_rmin[NROWS];     // warm-start row min (exact, +slack)
__device__ float              g_counts[KN];
__device__ float              g_dw[KN * DIM];
__device__ float              g_cs[KN];
__device__ float              g_losssum;
__device__ unsigned long long g_best[NROWS];     // (v_bits<<32)|code
__device__ unsigned           g_cand[CAND_CAP];  // (row<<12)|code
__device__ unsigned           g_ncand;
__device__ __nv_bfloat16      g_zb[NROWS * DIM];
__device__ __nv_bfloat16      g_eb[KN * DIM];

__device__ __forceinline__ unsigned smem_u32(const void* p) {
    unsigned r;
    asm("{ .reg .u64 t; cvta.to.shared.u64 t, %1; cvt.u32.u64 %0, t; }"
        : "=r"(r) : "l"(p));
    return r;
}

#define MMA16816(c, A, B0, B1) \
    asm volatile("mma.sync.aligned.m16n8k16.row.col.f32.bf16.bf16.f32 " \
        "{%0,%1,%2,%3}, {%4,%5,%6,%7}, {%8,%9}, {%0,%1,%2,%3};" \
        : "+f"((c)[0]), "+f"((c)[1]), "+f"((c)[2]), "+f"((c)[3]) \
        : "r"((A)[0]), "r"((A)[1]), "r"((A)[2]), "r"((A)[3]), \
          "r"(B0), "r"(B1))

#define CP_ASYNC8(dst, src) \
    asm volatile("cp.async.ca.shared.global [%0], [%1], 8;" \
        :: "r"(dst), "l"(src))

// ---------------------------------------------------------------------------
// K0a: zero g_dw, convert emb->bf16 (vectorized), ||e||^2 (exact reference
// rounding: sequential fadd_rn(fmul_rn), order preserved), counts, globals.
// ---------------------------------------------------------------------------
__global__ void k_prep_a(const float* __restrict__ emb) {
    int i = blockIdx.x * blockDim.x + threadIdx.x;   // 16384 threads
    #pragma unroll
    for (int it = 0; it < 4; it++) {
        int j = i + it * 16384;                      // 65536 uint4/uint2 slots
        ((uint4*)g_dw)[j] = make_uint4(0u, 0u, 0u, 0u);
        float4 v = __ldg((const float4*)emb + j);
        __nv_bfloat162 lo = __float22bfloat162_rn(make_float2(v.x, v.y));
        __nv_bfloat162 hi = __float22bfloat162_rn(make_float2(v.z, v.w));
        uint2 u;
        u.x = *(unsigned*)&lo;
        u.y = *(unsigned*)&hi;
        ((uint2*)g_eb)[j] = u;
    }
    if (i < KN) {
        g_counts[i] = 0.f;
        const float4* e4 = (const float4*)(emb + (size_t)i * DIM);
        float s = 0.f;
        #pragma unroll
        for (int q = 0; q < 16; q++) {
            float4 v = __ldg(e4 + q);
            s = __fadd_rn(s, __fmul_rn(v.x, v.x));
            s = __fadd_rn(s, __fmul_rn(v.y, v.y));
            s = __fadd_rn(s, __fmul_rn(v.z, v.z));
            s = __fadd_rn(s, __fmul_rn(v.w, v.w));
        }
        g_e2[i] = s;
    }
    if (i == 0) { g_losssum = 0.f; g_ncand = 0u; }
}

// ---------------------------------------------------------------------------
// K0b: convert z->bf16 (vectorized), ||z||^2 (sequential rounding), g_best.
// ---------------------------------------------------------------------------
__global__ void k_prep_b(const float* __restrict__ z) {
    int i = blockIdx.x * blockDim.x + threadIdx.x;   // 65536 threads
    #pragma unroll
    for (int it = 0; it < 8; it++) {
        int j = i + it * 65536;                      // 524288 float4 slots
        float4 v = __ldg((const float4*)z + j);
        __nv_bfloat162 lo = __float22bfloat162_rn(make_float2(v.x, v.y));
        __nv_bfloat162 hi = __float22bfloat162_rn(make_float2(v.z, v.w));
        uint2 u;
        u.x = *(unsigned*)&lo;
        u.y = *(unsigned*)&hi;
        ((uint2*)g_zb)[j] = u;
    }
    if (i < NROWS) {
        g_best[i] = 0xFFFFFFFFFFFFFFFFull;
        const float4* z4 = (const float4*)(z + (size_t)i * DIM);
        float s = 0.f;
        #pragma unroll
        for (int q = 0; q < 16; q++) {
            float4 v = __ldg(z4 + q);
            s = __fadd_rn(s, __fmul_rn(v.x, v.x));
            s = __fadd_rn(s, __fmul_rn(v.y, v.y));
            s = __fadd_rn(s, __fmul_rn(v.z, v.z));
            s = __fadd_rn(s, __fmul_rn(v.w, v.w));
        }
        g_zz[i] = s;
    }
}

// ---------------------------------------------------------------------------
// K0c: warm-start rowmin. Every row: exact fp32 s'=1+||e||^2-2 z.e over the
// SAME 32 sampled codes (smem-broadcast). +1e-4 slack covers exact-vs-bf16
// crossover at the threshold.
// ---------------------------------------------------------------------------
__global__ void k_warm(const float* __restrict__ z, const float* __restrict__ emb) {
    __shared__ float ec[32 * DIM];   // 8 KB sampled codes
    __shared__ float ee2[32];
    const int tid = threadIdx.x;     // 256
    for (int i = tid; i < 32 * DIM; i += 256) {
        int j = i >> 6, d = i & 63;
        ec[i] = __ldg(&emb[(size_t)(j * 128 + 64) * DIM + d]);
    }
    __syncthreads();
    if (tid < 32) {
        float s = 0.f;
        #pragma unroll
        for (int d = 0; d < DIM; d++) { float v = ec[tid * DIM + d]; s += v * v; }
        ee2[tid] = 1.0f + s;
    }
    __syncthreads();

    int row = blockIdx.x * 256 + tid;
    const float4* zr4 = (const float4*)(z + (size_t)row * DIM);
    float4 zl[16];
    #pragma unroll
    for (int q = 0; q < 16; q++) zl[q] = zr4[q];

    float best = FLT_MAX;
    #pragma unroll 4
    for (int j = 0; j < 32; j++) {
        const float4* e4 = (const float4*)(ec + j * DIM);
        float dot = 0.f;
        #pragma unroll
        for (int q = 0; q < 16; q++) {
            float4 e = e4[q];
            dot = fmaf(zl[q].x, e.x, dot);
            dot = fmaf(zl[q].y, e.y, dot);
            dot = fmaf(zl[q].z, e.z, dot);
            dot = fmaf(zl[q].w, e.w, dot);
        }
        best = fminf(best, fmaf(-2.f, dot, ee2[j]));
    }
    g_rmin[row] = best + 1e-4f;
}

// ---------------------------------------------------------------------------
// K1 (pass A): bf16 mma.sync distance scan + margin collection.
// Grid 1024: rb = bx>>2 (row block), kb = bx&3 (1024-code range, 8 chunks).
// 256 threads = 8 warps; warp_m = w>>1 (32 rows), warp_n = w&1 (64 codes).
// Local rowmin starts at the global warm bound; the winner's CTA always
// collects the winner (local min >= winner score within its range).
// ---------------------------------------------------------------------------
__global__ void __launch_bounds__(256, 3) k_passA() {
    extern __shared__ __align__(16) char smA[];
    __nv_bfloat16* zt = (__nv_bfloat16*)smA;                  // 9216 halves
    float*    e2s    = (float*)(smA + 55296);                 // 2*128 floats
    unsigned* rowmin = (unsigned*)(smA + 56320);              // 128

    const int tid  = threadIdx.x;
    const int lane = tid & 31;
    const int w    = tid >> 5;
    const int wm   = w >> 1;        // 0..3
    const int wn   = w & 1;         // 0..1
    const int gid  = lane >> 2;     // fragment row group
    const int qid  = lane & 3;      // fragment col pair
    const int rb   = blockIdx.x >> 2;
    const int kb   = blockIdx.x & 3;
    const int r0   = rb * AM;
    const int koff = kb * KPART;

    // ---- stage z tile (plain, once) ----
    const uint2* zb2 = (const uint2*)g_zb;
    #pragma unroll
    for (int it = 0; it < 8; it++) {
        int i  = tid + it * 256;       // 2048
        int r  = i >> 4;
        int c4 = i & 15;
        *(uint2*)(zt + r * LDT + c4 * 4) = zb2[(size_t)(r0 + r) * 16 + c4];
    }
    if (tid < AM) rowmin[tid] = __float_as_uint(__ldg(&g_rmin[r0 + tid]));

    // ---- prefetch e chunk 0 ----
    {
        unsigned etb = smem_u32(zt + 9216);
        const char* src0 = (const char*)g_eb + (size_t)koff * 64 * 2;
        #pragma unroll
        for (int it = 0; it < 8; it++) {
            int i  = tid + it * 256;
            int r  = i >> 4;
            int c4 = i & 15;
            CP_ASYNC8(etb + (unsigned)(r * LDT + c4 * 4) * 2,
                      src0 + ((size_t)r * 64 + c4 * 4) * 2);
        }
        asm volatile("cp.async.commit_group;");
        if (tid < ACH) e2s[tid] = __ldg(&g_e2[koff + tid]) + 1.0f;
    }
    __syncthreads();   // zt + rowmin visible

    // ---- A fragments (held across all chunks) ----
    unsigned a[2][4][4];
    {
        unsigned ztb = smem_u32(zt);
        #pragma unroll
        for (int tm = 0; tm < 2; tm++)
            #pragma unroll
            for (int kt = 0; kt < 4; kt++) {
                int R0 = wm * 32 + tm * 16;
                unsigned addr = ztb +
                    (unsigned)((R0 + (lane & 15)) * LDT + kt * 16 +
                               ((lane >> 4) << 3)) * 2;
                asm volatile(
                    "ldmatrix.sync.aligned.m8n8.x4.shared.b16 {%0,%1,%2,%3}, [%4];"
                    : "=r"(a[tm][kt][0]), "=r"(a[tm][kt][1]),
                      "=r"(a[tm][kt][2]), "=r"(a[tm][kt][3])
                    : "r"(addr));
            }
    }

    // thread's 4 row slots: slot = tm*2 + jh -> rl = wm*32 + tm*16 + gid + jh*8
    int rls[4];
    #pragma unroll
    for (int slot = 0; slot < 4; slot++)
        rls[slot] = wm * 32 + (slot >> 1) * 16 + gid + (slot & 1) * 8;

    for (int ch = 0; ch < NCHS; ch++) {
        asm volatile("cp.async.wait_group 0;");
        __syncthreads();   // current et/e2s visible; prev epilogue done

        if (ch + 1 < NCHS) {
            int nb2 = (ch + 1) & 1;
            unsigned etb = smem_u32(zt + 9216 + nb2 * 9216);
            const char* src = (const char*)g_eb +
                              (size_t)(koff + (ch + 1) * ACH) * 64 * 2;
            #pragma unroll
            for (int it = 0; it < 8; it++) {
                int i  = tid + it * 256;
                int r  = i >> 4;
                int c4 = i & 15;
                CP_ASYNC8(etb + (unsigned)(r * LDT + c4 * 4) * 2,
                          src + ((size_t)r * 64 + c4 * 4) * 2);
            }
            asm volatile("cp.async.commit_group;");
            if (tid < ACH)
                e2s[nb2 * ACH + tid] =
                    __ldg(&g_e2[koff + (ch + 1) * ACH + tid]) + 1.0f;
        }

        // per-chunk thresholds (stale-read safe: only over-collects)
        float thr[4], lmin[4];
        #pragma unroll
        for (int slot = 0; slot < 4; slot++) {
            thr[slot]  = __uint_as_float(rowmin[rls[slot]]) + MARGIN;
            lmin[slot] = FLT_MAX;
        }

        const int cb = ch & 1;
        unsigned et_base = smem_u32(zt + 9216 + cb * 9216);
        const float* e2c = e2s + cb * ACH;

        #pragma unroll
        for (int nt = 0; nt < 8; nt++) {
            const int nb = wn * 64 + nt * 8;

            unsigned b0[4], b1[4];
            #pragma unroll
            for (int kt = 0; kt < 4; kt++) {
                unsigned addr = et_base +
                    (unsigned)((nb + (lane & 7)) * LDT + kt * 16 +
                               (((lane >> 3) & 1) << 3)) * 2;
                asm volatile(
                    "ldmatrix.sync.aligned.m8n8.x2.shared.b16 {%0,%1}, [%2];"
                    : "=r"(b0[kt]), "=r"(b1[kt]) : "r"(addr));
            }

            float c0[4] = {0.f, 0.f, 0.f, 0.f};
            float c1[4] = {0.f, 0.f, 0.f, 0.f};
            #pragma unroll
            for (int kt = 0; kt < 4; kt++) {
                MMA16816(c0, a[0][kt], b0[kt], b1[kt]);
                MMA16816(c1, a[1][kt], b0[kt], b1[kt]);
            }

            const float e2p0 = e2c[nb + qid * 2];
            const float e2p1 = e2c[nb + qid * 2 + 1];

            #pragma unroll
            for (int tm = 0; tm < 2; tm++) {
                const float* cc = tm ? c1 : c0;
                #pragma unroll
                for (int jh = 0; jh < 2; jh++) {
                    int slot = tm * 2 + jh;
                    float s0 = fmaf(-2.f, cc[jh * 2],     e2p0);
                    float s1 = fmaf(-2.f, cc[jh * 2 + 1], e2p1);
                    float m2 = fminf(s0, s1);
                    lmin[slot] = fminf(lmin[slot], m2);
                    if (m2 <= thr[slot]) {                  // rare
                        unsigned codeb =
                            (unsigned)(koff + ch * ACH + nb + qid * 2);
                        unsigned rw = (unsigned)(r0 + rls[slot]) << 12;
                        if (s0 <= thr[slot]) {
                            unsigned pos = atomicAdd(&g_ncand, 1u);
                            if (pos < CAND_CAP) g_cand[pos] = rw | codeb;
                        }
                        if (s1 <= thr[slot]) {
                            unsigned pos = atomicAdd(&g_ncand, 1u);
                            if (pos < CAND_CAP) g_cand[pos] = rw | (codeb + 1);
                        }
                    }
                }
            }
        }

        // fold chunk minima into shared rowmin (visible next chunk via sync)
        #pragma unroll
        for (int slot = 0; slot < 4; slot++)
            atomicMin(&rowmin[rls[slot]], __float_as_uint(lmin[slot]));
    }
}

// ---------------------------------------------------------------------------
// K2 (pass B): exact reference-rounded rescreen, 8 lanes/candidate,
// TWO candidates in flight per group (loads batched up front for ILP).
// Final rounding unchanged: v = fsub_rn(fadd_rn(zz,ee), 2*dot); winner via
// atomicMin on (v_bits<<32)|code. Association safety: dot err ~1e-9 <<
// ulp(64)~7.6e-6 grid (empirically verified R8->R10: identical rel_err).
// ---------------------------------------------------------------------------
__global__ void k_rescreen(const float* __restrict__ z,
                           const float* __restrict__ emb) {
    unsigned n = g_ncand;
    if (n > CAND_CAP) n = CAND_CAP;
    const int ln  = threadIdx.x & 31;
    const int sub = ln >> 3;            // candidate slot within warp
    const int sl  = ln & 7;             // lane within candidate group
    const unsigned gmask = 0xFFu << (sub * 8);
    const unsigned gw = (blockIdx.x * blockDim.x + threadIdx.x) >> 5;
    const unsigned nw = (gridDim.x * blockDim.x) >> 5;

    for (unsigned base = gw * 8; base < n; base += nw * 8) {
        unsigned i0 = base + (unsigned)sub;
        unsigned i1 = base + 4u + (unsigned)sub;
        bool ok0 = i0 < n, ok1 = i1 < n;
        unsigned j0 = ok0 ? i0 : 0u, j1 = ok1 ? i1 : 0u;
        unsigned cd0 = __ldg(&g_cand[j0]);
        unsigned cd1 = __ldg(&g_cand[j1]);
        unsigned row0 = cd0 >> 12, code0 = cd0 & 4095u;
        unsigned row1 = cd1 >> 12, code1 = cd1 & 4095u;
        const float4* zr0 = (const float4*)(z   + (size_t)row0  * DIM) + sl * 2;
        const float4* er0 = (const float4*)(emb + (size_t)code0 * DIM) + sl * 2;
        const float4* zr1 = (const float4*)(z   + (size_t)row1  * DIM) + sl * 2;
        const float4* er1 = (const float4*)(emb + (size_t)code1 * DIM) + sl * 2;
        float4 a0 = __ldg(zr0), a1 = __ldg(zr0 + 1);
        float4 b0 = __ldg(er0), b1 = __ldg(er0 + 1);
        float4 a2 = __ldg(zr1), a3 = __ldg(zr1 + 1);
        float4 b2 = __ldg(er1), b3 = __ldg(er1 + 1);
        float p0 = __fmul_rn(a0.x, b0.x);
        float p1 = __fmul_rn(a2.x, b2.x);
        p0 = __fmaf_rn(a0.y, b0.y, p0); p1 = __fmaf_rn(a2.y, b2.y, p1);
        p0 = __fmaf_rn(a0.z, b0.z, p0); p1 = __fmaf_rn(a2.z, b2.z, p1);
        p0 = __fmaf_rn(a0.w, b0.w, p0); p1 = __fmaf_rn(a2.w, b2.w, p1);
        p0 = __fmaf_rn(a1.x, b1.x, p0); p1 = __fmaf_rn(a3.x, b3.x, p1);
        p0 = __fmaf_rn(a1.y, b1.y, p0); p1 = __fmaf_rn(a3.y, b3.y, p1);
        p0 = __fmaf_rn(a1.z, b1.z, p0); p1 = __fmaf_rn(a3.z, b3.z, p1);
        p0 = __fmaf_rn(a1.w, b1.w, p0); p1 = __fmaf_rn(a3.w, b3.w, p1);
        p0 += __shfl_xor_sync(gmask, p0, 1);
        p1 += __shfl_xor_sync(gmask, p1, 1);
        p0 += __shfl_xor_sync(gmask, p0, 2);
        p1 += __shfl_xor_sync(gmask, p1, 2);
        p0 += __shfl_xor_sync(gmask, p0, 4);
        p1 += __shfl_xor_sync(gmask, p1, 4);
        if (sl == 0) {
            if (ok0) {
                float v = __fsub_rn(
                    __fadd_rn(__ldg(&g_zz[row0]), __ldg(&g_e2[code0])),
                    __fmul_rn(2.f, p0));
                unsigned long long key =
                    ((unsigned long long)__float_as_uint(v) << 32) | code0;
                atomicMin(&g_best[row0], key);
            }
            if (ok1) {
                float v = __fsub_rn(
                    __fadd_rn(__ldg(&g_zz[row1]), __ldg(&g_e2[code1])),
                    __fmul_rn(2.f, p1));
                unsigned long long key =
                    ((unsigned long long)__float_as_uint(v) << 32) | code1;
                atomicMin(&g_best[row1], key);
            }
        }
    }
}

// ---------------------------------------------------------------------------
// K3: gather z_q, straight-through output, loss partial, scatter counts/dw.
// ---------------------------------------------------------------------------
__global__ void k_scatter(const float* __restrict__ z, const float* __restrict__ emb,
                          float* __restrict__ out)
{
    int row = blockIdx.x * 8 + (threadIdx.x >> 5);
    int ln  = threadIdx.x & 31;
    int idx = (int)(unsigned)(g_best[row] & 0xffffffffull);
    const float* zr = z   + (size_t)row * DIM;
    const float* er = emb + (size_t)idx * DIM;
    float* zq = out + O_ZQ + (size_t)row * DIM;
    float l = 0.f;
    #pragma unroll
    for (int t = 0; t < 2; t++) {
        int j = ln + 32 * t;
        float zv = zr[j], ev = __ldg(er + j);
        zq[j] = __fadd_rn(zv, __fsub_rn(ev, zv));
        float dd = __fsub_rn(zv, ev);
        l += dd * dd;
        atomicAdd(&g_dw[idx * DIM + j], zv);
    }
    if (ln == 0) {
        atomicAdd(&g_counts[idx], 1.f);
        out[O_IND + row] = (float)idx;
    }
    #pragma unroll
    for (int o = 16; o; o >>= 1) l += __shfl_xor_sync(0xffffffffu, l, o);
    __shared__ float sl2[8];
    if (ln == 0) sl2[threadIdx.x >> 5] = l;
    __syncthreads();
    if (threadIdx.x == 0) {
        float s = 0.f;
        #pragma unroll
        for (int w2 = 0; w2 < 8; w2++) s += sl2[w2];
        atomicAdd(&g_losssum, s);
    }
}

// ---------------------------------------------------------------------------
// K4: new_cluster_size, n, normalized cluster size, loss (single block)
// ---------------------------------------------------------------------------
__global__ void k_fin1(const float* __restrict__ ema_cs, float* __restrict__ out)
{
    int tid = threadIdx.x;  // 1024
    float ncs[4];
    float s = 0.f;
    #pragma unroll
    for (int j = 0; j < 4; j++) {
        int k = tid + j * 1024;
        float v = 0.99f * ema_cs[k] + 0.01f * g_counts[k];
        ncs[j] = v; s += v;
        out[O_NCS + k] = v;
    }
    __shared__ float sp[32];
    #pragma unroll
    for (int o = 16; o; o >>= 1) s += __shfl_xor_sync(0xffffffffu, s, o);
    if ((tid & 31) == 0) sp[tid >> 5] = s;
    __syncthreads();
    if (tid < 32) {
        float v = sp[tid];
        #pragma unroll
        for (int o = 16; o; o >>= 1) v += __shfl_xor_sync(0xffffffffu, v, o);
        if (tid == 0) sp[0] = v;
    }
    __syncthreads();
    float n = sp[0];
    float denom = n + (float)KN * 1e-5f;
    #pragma unroll
    for (int j = 0; j < 4; j++) {
        int k = tid + j * 1024;
        g_cs[k] = (ncs[j] + 1e-5f) / denom * n;
    }
    if (tid == 0) out[O_LOSS] = 0.25f * (g_losssum / 2097152.0f);
}

// ---------------------------------------------------------------------------
// K5: new_ema_w and new_embedding
// ---------------------------------------------------------------------------
__global__ void k_fin2(const float* __restrict__ ema_w, float* __restrict__ out)
{
    int i = blockIdx.x * blockDim.x + threadIdx.x;   // 262144 total
    float nw = 0.99f * ema_w[i] + 0.01f * g_dw[i];
    out[O_NW + i] = nw;
    out[O_NE + i] = __fdiv_rn(nw, g_cs[i >> 6]);
}

// ---------------------------------------------------------------------------
#define SMA_BYTES 56832

extern "C" void kernel_launch(void* const* d_in, const int* in_sizes, int n_in,
                              void* d_out, int out_size)
{
    const float* z      = (const float*)d_in[0];
    const float* emb    = (const float*)d_in[1];
    const float* ema_cs = (const float*)d_in[2];
    const float* ema_w  = (const float*)d_in[3];
    float* out = (float*)d_out;

    cudaFuncSetAttribute(k_passA, cudaFuncAttributeMaxDynamicSharedMemorySize,
                         SMA_BYTES);

    k_prep_a  <<<64, 256>>>(emb);                 // launch 0
    k_prep_b  <<<256, 256>>>(z);                  // launch 1
    k_warm    <<<NROWS / 256, 256>>>(z, emb);     // launch 2
    k_passA   <<<ABLK, 256, SMA_BYTES>>>();       // launch 3  <- profiled
    k_rescreen<<<1024, 256>>>(z, emb);            // launch 4
    k_scatter <<<NROWS / 8, 256>>>(z, emb, out);  // launch 5
    k_fin1    <<<1, 1024>>>(ema_cs, out);         // launch 6
    k_fin2    <<<KN * DIM / 256, 256>>>(ema_w, out); // launch 7
}